// round 12
// baseline (speedup 1.0000x reference)
#include <cuda_runtime.h>
#include <cuda_fp16.h>
#include <cstdint>
#include <cstddef>

// Problem constants
#define S_   2048
#define E_   512
#define H_   8
#define DH_  64
#define B_   2
#define BH_  16          // B_*H_
#define SCALE_ 0.125f    // DH^-0.5

// ---------------- scratch (__device__ globals: allocation-free) ----------------
__device__ float    g_Q  [BH_ * S_ * DH_];          // 8 MB
__device__ float    g_K  [BH_ * S_ * DH_];          // 8 MB
__device__ float    g_V  [BH_ * S_ * DH_];          // 8 MB
__device__ float    g_O  [BH_ * S_ * DH_];          // 8 MB
__device__ __half   g_WLDh[(size_t)S_ * S_];        // 8 MB: exp(-layer_distances) in fp16
__device__ unsigned g_MPK[(size_t)S_ * S_ / 32];    // 512 KB: mask packed 1 bit/elem
__device__ float    g_RP [(size_t)BH_ * S_ * 32];   // 4 MB: per-row partial sums (32 n-blocks)
__device__ __half   g_Eh [(size_t)BH_ * S_ * S_];   // 134 MB: unnormalized exp-scores (fp16)
__device__ float    g_Pfb[(size_t)BH_ * S_ * S_];   // 268 MB fallback if weights not in d_out
__device__ float    g_AOfb[B_ * S_ * E_];           // fallback attn_output sink

// ---------------- tf32 mma helpers ----------------
__device__ __forceinline__ uint32_t f2tf(float x) {
    uint32_t u;
    asm("cvt.rna.tf32.f32 %0, %1;" : "=r"(u) : "f"(x));
    return u;
}

// hi/lo split for 3xTF32: x ~= hi + lo, both exactly representable in tf32.
__device__ __forceinline__ void split_tf(float x, uint32_t& hi, uint32_t& lo) {
    hi = f2tf(x);
    lo = f2tf(x - __uint_as_float(hi));
}

__device__ __forceinline__ void mma8(float c[4], const uint32_t a[4], const uint32_t b[2]) {
    asm volatile(
        "mma.sync.aligned.m16n8k8.row.col.f32.tf32.tf32.f32 "
        "{%0,%1,%2,%3},{%4,%5,%6,%7},{%8,%9},{%0,%1,%2,%3};"
        : "+f"(c[0]), "+f"(c[1]), "+f"(c[2]), "+f"(c[3])
        : "r"(a[0]), "r"(a[1]), "r"(a[2]), "r"(a[3]), "r"(b[0]), "r"(b[1]));
}

// streaming (evict-first) load/store helpers
__device__ __forceinline__ void stcs4(float* p, float4 v) { __stcs((float4*)p, v); }
__device__ __forceinline__ void stcsu(unsigned* p, unsigned v) { __stcs(p, v); }
__device__ __forceinline__ uint2 ldcs_u2(const void* p) { return __ldcs((const uint2*)p); }

// 64x64 block tile, 4 warps (2x2), each warp 32x32 = 2(m) x 4(n) m16n8k8 tiles.
// Smem tiles are [64][36] (stride-36 pad -> conflict-free fragment loads:
// bank = (4*grp + tig + kk) % 32, all lanes distinct).
// 3xTF32 variant: ~fp32 accuracy. ah*bh + ah*bl + al*bh.
__device__ __forceinline__ void mma_tile3x(const float As[64][36], const float Bs[64][36],
                                           float acc[2][4][4], int wm, int wn, int grp, int tig) {
#pragma unroll
    for (int kk = 0; kk < 32; kk += 8) {
        uint32_t ah[2][4], al[2][4], bh[4][2], bl[4][2];
#pragma unroll
        for (int mt = 0; mt < 2; mt++) {
            int r = wm * 32 + mt * 16 + grp;
            split_tf(As[r    ][kk + tig    ], ah[mt][0], al[mt][0]);
            split_tf(As[r + 8][kk + tig    ], ah[mt][1], al[mt][1]);
            split_tf(As[r    ][kk + tig + 4], ah[mt][2], al[mt][2]);
            split_tf(As[r + 8][kk + tig + 4], ah[mt][3], al[mt][3]);
        }
#pragma unroll
        for (int nt = 0; nt < 4; nt++) {
            int c = wn * 32 + nt * 8 + grp;
            split_tf(Bs[c][kk + tig    ], bh[nt][0], bl[nt][0]);
            split_tf(Bs[c][kk + tig + 4], bh[nt][1], bl[nt][1]);
        }
#pragma unroll
        for (int mt = 0; mt < 2; mt++)
#pragma unroll
            for (int nt = 0; nt < 4; nt++) {
                mma8(acc[mt][nt], ah[mt], bl[nt]);
                mma8(acc[mt][nt], al[mt], bh[nt]);
                mma8(acc[mt][nt], ah[mt], bh[nt]);
            }
    }
}

// ---------------- kernel 0a: WLDh = half(exp(-layer_distances)), computed once --------------
__global__ __launch_bounds__(256) void expld_kernel(const float* __restrict__ ld,
                                                    __half* __restrict__ w) {
    size_t i = ((size_t)blockIdx.x * 256 + threadIdx.x) * 8;
    float4 a = *(const float4*)&ld[i];
    float4 b = *(const float4*)&ld[i + 4];
    __half2 h0 = __floats2half2_rn(__expf(-a.x), __expf(-a.y));
    __half2 h1 = __floats2half2_rn(__expf(-a.z), __expf(-a.w));
    __half2 h2 = __floats2half2_rn(__expf(-b.x), __expf(-b.y));
    __half2 h3 = __floats2half2_rn(__expf(-b.z), __expf(-b.w));
    uint4 o;
    o.x = *reinterpret_cast<uint32_t*>(&h0);
    o.y = *reinterpret_cast<uint32_t*>(&h1);
    o.z = *reinterpret_cast<uint32_t*>(&h2);
    o.w = *reinterpret_cast<uint32_t*>(&h3);
    *reinterpret_cast<uint4*>(w + i) = o;
}

// ---------------- kernel 0b: pack mask to 1 bit/element, computed once ----------------
__global__ __launch_bounds__(256) void packmask_kernel(const int* __restrict__ mask,
                                                       unsigned* __restrict__ mpk) {
    int w = blockIdx.x * 256 + threadIdx.x;
    const int* base = mask + (size_t)w * 32;
    unsigned bits = 0;
#pragma unroll
    for (int j = 0; j < 8; j++) {
        int4 v = *(const int4*)(base + j * 4);
        bits |= (v.x != 0 ? 1u : 0u) << (j * 4 + 0);
        bits |= (v.y != 0 ? 1u : 0u) << (j * 4 + 1);
        bits |= (v.z != 0 ? 1u : 0u) << (j * 4 + 2);
        bits |= (v.w != 0 ? 1u : 0u) << (j * 4 + 3);
    }
    mpk[w] = bits;
}

// ---------------- kernel 1: fused QKV projection (3xTF32, double-buffered) ----------------
// blockIdx.z in {0,1,2} selects (X, W, bias, out). grid (8, 64, 3), 128 threads.
// Register prefetch of the k+1 tiles overlaps L2 latency with the mma work.
__global__ __launch_bounds__(128) void qkv_kernel(
    const float* __restrict__ Xq, const float* __restrict__ Xk, const float* __restrict__ Xv,
    const float* __restrict__ Wq, const float* __restrict__ Wk, const float* __restrict__ Wv,
    const float* __restrict__ bq, const float* __restrict__ bk, const float* __restrict__ bv,
    float* __restrict__ oq, float* __restrict__ ok, float* __restrict__ ov) {
    const int z = blockIdx.z;
    const float* X    = (z == 0) ? Xq : (z == 1) ? Xk : Xv;
    const float* W    = (z == 0) ? Wq : (z == 1) ? Wk : Wv;
    const float* bias = (z == 0) ? bq : (z == 1) ? bk : bv;
    float*       out  = (z == 0) ? oq : (z == 1) ? ok : ov;

    __shared__ float As[64][36];
    __shared__ float Bs[64][36];
    const int t = threadIdx.x;
    const int lane = t & 31, warp = t >> 5;
    const int wm = warp >> 1, wn = warp & 1;
    const int grp = lane >> 2, tig = lane & 3;
    const int m0 = blockIdx.y * 64, n0 = blockIdx.x * 64;

    int rowT[4], c4T[4];
#pragma unroll
    for (int i = 0; i < 4; i++) {
        int idx = t + i * 128;
        rowT[i] = idx >> 3; c4T[i] = idx & 7;
    }

    // prologue prefetch k0 = 0
    float4 xR[4], wR[4];
#pragma unroll
    for (int i = 0; i < 4; i++) {
        xR[i] = *(const float4*)&X[(size_t)(m0 + rowT[i]) * 512 + c4T[i] * 4];
        wR[i] = *(const float4*)&W[(size_t)(n0 + rowT[i]) * 512 + c4T[i] * 4];
    }

    float acc[2][4][4] = {};
    for (int k0 = 0; k0 < 512; k0 += 32) {
#pragma unroll
        for (int i = 0; i < 4; i++) {
            *(float4*)&As[rowT[i]][c4T[i] * 4] = xR[i];
            *(float4*)&Bs[rowT[i]][c4T[i] * 4] = wR[i];
        }
        if (k0 + 32 < 512) {
#pragma unroll
            for (int i = 0; i < 4; i++) {
                xR[i] = *(const float4*)&X[(size_t)(m0 + rowT[i]) * 512 + (k0 + 32) + c4T[i] * 4];
                wR[i] = *(const float4*)&W[(size_t)(n0 + rowT[i]) * 512 + (k0 + 32) + c4T[i] * 4];
            }
        }
        __syncthreads();
        mma_tile3x(As, Bs, acc, wm, wn, grp, tig);
        __syncthreads();
    }
#pragma unroll
    for (int mt = 0; mt < 2; mt++) {
#pragma unroll
        for (int nt = 0; nt < 4; nt++) {
            int n = n0 + wn * 32 + nt * 8 + tig * 2;
            float bv0 = bias[n], bv1 = bias[n + 1];
            int h = n >> 6, d = n & 63;
#pragma unroll
            for (int rr = 0; rr < 2; rr++) {
                int m = m0 + wm * 32 + mt * 16 + grp + rr * 8;
                int bb = m >> 11, s = m & 2047;
                float2 o;
                o.x = acc[mt][nt][rr * 2 + 0] + bv0;
                o.y = acc[mt][nt][rr * 2 + 1] + bv1;
                *(float2*)&out[(((size_t)(bb * H_ + h)) * S_ + s) * DH_ + d] = o;
            }
        }
    }
}

// ---------------- kernel 2: Eh = half(exp(QK^T*SCALE + tb[h]*WLD)), mask->0 (3xTF32) --------
// Row partial sums (RP) computed from fp32 values BEFORE fp16 quantization.
// Eh stores are streaming; wld/mpk stay L2-resident across the 16 bh passes.
// Per (b,h): grid (32, 32, 16), 128 threads.
__global__ __launch_bounds__(128) void scores_kernel(
    const float* __restrict__ Q, const float* __restrict__ Kt,
    const unsigned* __restrict__ mpk, const __half2* __restrict__ wldh,
    const float* __restrict__ tb, __half* __restrict__ Eh, float* __restrict__ RP) {
    __shared__ float As[64][36];
    __shared__ float Bs[64][36];
    __shared__ float sumbuf[64][2];
    const int t = threadIdx.x;
    const int lane = t & 31, warp = t >> 5;
    const int wm = warp >> 1, wn = warp & 1;
    const int grp = lane >> 2, tig = lane & 3;
    const int bh = blockIdx.z;
    const float* Qb  = Q  + (size_t)bh * S_ * DH_;
    const float* Kb  = Kt + (size_t)bh * S_ * DH_;
    __half*      Eb  = Eh + (size_t)bh * S_ * S_;
    const float  tbh = tb[bh & (H_ - 1)];
    const int m0 = blockIdx.y * 64, n0 = blockIdx.x * 64;

    float acc[2][4][4] = {};
    for (int k0 = 0; k0 < 64; k0 += 32) {
#pragma unroll
        for (int i = 0; i < 4; i++) {
            int idx = t + i * 128, row = idx >> 3, c4 = idx & 7;
            *(float4*)&As[row][c4 * 4] = *(const float4*)&Qb[(size_t)(m0 + row) * 64 + k0 + c4 * 4];
            *(float4*)&Bs[row][c4 * 4] = *(const float4*)&Kb[(size_t)(n0 + row) * 64 + k0 + c4 * 4];
        }
        __syncthreads();
        mma_tile3x(As, Bs, acc, wm, wn, grp, tig);
        __syncthreads();
    }
#pragma unroll
    for (int mt = 0; mt < 2; mt++) {
#pragma unroll
        for (int rr = 0; rr < 2; rr++) {
            const int m = m0 + wm * 32 + mt * 16 + grp + rr * 8;
            // one packed-mask word covers this row's 32-column half-tile (n0 multiple of 64)
            const unsigned mw = mpk[m * (S_ / 32) + (n0 >> 5) + wn];
            float psum = 0.f;
#pragma unroll
            for (int nt = 0; nt < 4; nt++) {
                int n = n0 + wn * 32 + nt * 8 + tig * 2;
                size_t idx = (size_t)m * S_ + n;
                float2 wv = __half22float2(wldh[idx >> 1]);
                int bit = nt * 8 + tig * 2;
                float s0 = acc[mt][nt][rr * 2 + 0] * SCALE_ + tbh * wv.x;
                float s1 = acc[mt][nt][rr * 2 + 1] * SCALE_ + tbh * wv.y;
                float ex = ((mw >> bit) & 1u)       ? __expf(s0) : 0.f;
                float ey = ((mw >> (bit + 1)) & 1u) ? __expf(s1) : 0.f;
                __half2 hh = __floats2half2_rn(ex, ey);
                stcsu((unsigned*)&Eb[idx], *reinterpret_cast<unsigned*>(&hh));
                psum += ex + ey;   // fp32 sum, pre-quantization
            }
            // reduce across the 4-lane tig group (deterministic order)
            psum += __shfl_xor_sync(0xffffffffu, psum, 1);
            psum += __shfl_xor_sync(0xffffffffu, psum, 2);
            if (tig == 0) sumbuf[m - m0][wn] = psum;
        }
    }
    __syncthreads();
    if (t < 64) {
        RP[((size_t)bh * S_ + (m0 + t)) * 32 + blockIdx.x] = sumbuf[t][0] + sumbuf[t][1];
    }
}

// ---------------- kernel 3: read half E, write normalized fp32 P, O = Pn @ V ----------------
// grid (1, 32, 16). E read and P write both streaming; V stays cached.
// Register double-buffer: E/V for k-step k0+32 are prefetched right after the
// smem-store phase of k0, so DRAM latency overlaps the mma + barriers.
__global__ __launch_bounds__(128) void av_kernel(
    const __half* __restrict__ Eh, const float* __restrict__ V,
    const float* __restrict__ RP, float* __restrict__ Pout, float* __restrict__ O) {
    __shared__ float As[64][36];
    __shared__ float Bk[32][68];
    __shared__ float invs[64];
    const int t = threadIdx.x;
    const int lane = t & 31, warp = t >> 5;
    const int wm = warp >> 1, wn = warp & 1;
    const int grp = lane >> 2, tig = lane & 3;
    const int bh = blockIdx.z;
    const __half* Eb = Eh   + (size_t)bh * S_ * S_;
    float*        Pb = Pout + (size_t)bh * S_ * S_;
    const float*  Vb = V    + (size_t)bh * S_ * DH_;
    float*        Ob = O    + (size_t)bh * S_ * DH_;
    const int m0 = blockIdx.y * 64;

    // deterministic row sums: serial add of the 32 partials per row
    if (t < 64) {
        const float* rp = RP + ((size_t)bh * S_ + (m0 + t)) * 32;
        float s = 0.f;
#pragma unroll
        for (int j = 0; j < 32; j++) s += rp[j];
        invs[t] = 1.0f / s;
    }
    __syncthreads();

    // fixed per-thread tile coordinates
    int rowE[4], c4E[4], kkV[4], c4V[4];
#pragma unroll
    for (int i = 0; i < 4; i++) {
        int idx = t + i * 128;
        rowE[i] = idx >> 3;  c4E[i] = idx & 7;    // E: 64 rows x 8 float4-chunks
        kkV[i]  = idx >> 4;  c4V[i] = idx & 15;   // V: 32 rows x 16 float4-chunks
    }

    // prologue: prefetch k0 = 0
    uint2  eR[4];
    float4 vR[4];
#pragma unroll
    for (int i = 0; i < 4; i++) {
        eR[i] = ldcs_u2(&Eb[(size_t)(m0 + rowE[i]) * S_ + c4E[i] * 4]);
        vR[i] = *(const float4*)&Vb[(size_t)kkV[i] * 64 + c4V[i] * 4];
    }

    float acc[2][4][4] = {};
    for (int k0 = 0; k0 < S_; k0 += 32) {
        // store phase: consume eR/vR (previous mma done per trailing barrier)
#pragma unroll
        for (int i = 0; i < 4; i++) {
            float2 e01 = __half22float2(*reinterpret_cast<__half2*>(&eR[i].x));
            float2 e23 = __half22float2(*reinterpret_cast<__half2*>(&eR[i].y));
            float iv = invs[rowE[i]];
            float4 v;
            v.x = e01.x * iv; v.y = e01.y * iv;
            v.z = e23.x * iv; v.w = e23.y * iv;
            *(float4*)&As[rowE[i]][c4E[i] * 4] = v;
            stcs4(&Pb[(size_t)(m0 + rowE[i]) * S_ + k0 + c4E[i] * 4], v);
            *(float4*)&Bk[kkV[i]][c4V[i] * 4] = vR[i];
        }
        // prefetch next k-step (overlaps with barriers + mma below)
        if (k0 + 32 < S_) {
#pragma unroll
            for (int i = 0; i < 4; i++) {
                eR[i] = ldcs_u2(&Eb[(size_t)(m0 + rowE[i]) * S_ + (k0 + 32) + c4E[i] * 4]);
                vR[i] = *(const float4*)&Vb[(size_t)(k0 + 32 + kkV[i]) * 64 + c4V[i] * 4];
            }
        }
        __syncthreads();
#pragma unroll
        for (int kk = 0; kk < 32; kk += 8) {
            uint32_t a[2][4], b[4][2];
#pragma unroll
            for (int mt = 0; mt < 2; mt++) {
                int r = wm * 32 + mt * 16 + grp;
                a[mt][0] = f2tf(As[r    ][kk + tig    ]);
                a[mt][1] = f2tf(As[r + 8][kk + tig    ]);
                a[mt][2] = f2tf(As[r    ][kk + tig + 4]);
                a[mt][3] = f2tf(As[r + 8][kk + tig + 4]);
            }
#pragma unroll
            for (int nt = 0; nt < 4; nt++) {
                int c = wn * 32 + nt * 8 + grp;
                b[nt][0] = f2tf(Bk[kk + tig    ][c]);
                b[nt][1] = f2tf(Bk[kk + tig + 4][c]);
            }
#pragma unroll
            for (int mt = 0; mt < 2; mt++)
#pragma unroll
                for (int nt = 0; nt < 4; nt++)
                    mma8(acc[mt][nt], a[mt], b[nt]);
        }
        __syncthreads();
    }
#pragma unroll
    for (int mt = 0; mt < 2; mt++) {
#pragma unroll
        for (int nt = 0; nt < 4; nt++) {
            int n = wn * 32 + nt * 8 + tig * 2;
#pragma unroll
            for (int rr = 0; rr < 2; rr++) {
                int m = m0 + wm * 32 + mt * 16 + grp + rr * 8;
                float2 o;
                o.x = acc[mt][nt][rr * 2 + 0];
                o.y = acc[mt][nt][rr * 2 + 1];
                *(float2*)&Ob[(size_t)m * 64 + n] = o;
            }
        }
    }
}

// ---------------- kernel 4: output projection (head-gather A, 3xTF32, double-buffered) ------
// A[m,k] = O_heads[b,h,s,d] with m=b*S+s, k=h*64+d.  grid (8, 64).
__global__ __launch_bounds__(128) void oproj_kernel(
    const float* __restrict__ O, const float* __restrict__ W,
    const float* __restrict__ bias, float* __restrict__ out) {
    __shared__ float As[64][36];
    __shared__ float Bs[64][36];
    const int t = threadIdx.x;
    const int lane = t & 31, warp = t >> 5;
    const int wm = warp >> 1, wn = warp & 1;
    const int grp = lane >> 2, tig = lane & 3;
    const int m0 = blockIdx.y * 64, n0 = blockIdx.x * 64;

    int rowT[4], c4T[4];
#pragma unroll
    for (int i = 0; i < 4; i++) {
        int idx = t + i * 128;
        rowT[i] = idx >> 3; c4T[i] = idx & 7;
    }

    // gathered A load for k-step k0 (h-segment per float4 chunk)
    auto loadA = [&](int i, int k0) -> float4 {
        int m = m0 + rowT[i];
        int bb = m >> 11, s = m & 2047;
        int kk = k0 + c4T[i] * 4;
        int h = kk >> 6, d = kk & 63;
        return *(const float4*)&O[(((size_t)(bb * H_ + h)) * S_ + s) * DH_ + d];
    };

    // prologue prefetch k0 = 0
    float4 aR[4], wR[4];
#pragma unroll
    for (int i = 0; i < 4; i++) {
        aR[i] = loadA(i, 0);
        wR[i] = *(const float4*)&W[(size_t)(n0 + rowT[i]) * 512 + c4T[i] * 4];
    }

    float acc[2][4][4] = {};
    for (int k0 = 0; k0 < 512; k0 += 32) {
#pragma unroll
        for (int i = 0; i < 4; i++) {
            *(float4*)&As[rowT[i]][c4T[i] * 4] = aR[i];
            *(float4*)&Bs[rowT[i]][c4T[i] * 4] = wR[i];
        }
        if (k0 + 32 < 512) {
#pragma unroll
            for (int i = 0; i < 4; i++) {
                aR[i] = loadA(i, k0 + 32);
                wR[i] = *(const float4*)&W[(size_t)(n0 + rowT[i]) * 512 + (k0 + 32) + c4T[i] * 4];
            }
        }
        __syncthreads();
        mma_tile3x(As, Bs, acc, wm, wn, grp, tig);
        __syncthreads();
    }
#pragma unroll
    for (int mt = 0; mt < 2; mt++) {
#pragma unroll
        for (int nt = 0; nt < 4; nt++) {
            int n = n0 + wn * 32 + nt * 8 + tig * 2;
            float bv0 = bias[n], bv1 = bias[n + 1];
#pragma unroll
            for (int rr = 0; rr < 2; rr++) {
                int m = m0 + wm * 32 + mt * 16 + grp + rr * 8;
                float2 o;
                o.x = acc[mt][nt][rr * 2 + 0] + bv0;
                o.y = acc[mt][nt][rr * 2 + 1] + bv1;
                *(float2*)&out[(size_t)m * 512 + n] = o;
            }
        }
    }
}

// ---------------- host launcher ----------------
extern "C" void kernel_launch(void* const* d_in, const int* in_sizes, int n_in,
                              void* d_out, int out_size) {
    const float* query = (const float*)d_in[0];
    const float* key   = (const float*)d_in[1];
    const float* value = (const float*)d_in[2];
    const int*   mask  = (const int*)d_in[3];
    const float* ld    = (const float*)d_in[4];
    const float* Wq    = (const float*)d_in[5];
    const float* bq    = (const float*)d_in[6];
    const float* Wk    = (const float*)d_in[7];
    const float* bk    = (const float*)d_in[8];
    const float* Wv    = (const float*)d_in[9];
    const float* bv    = (const float*)d_in[10];
    const float* Wo    = (const float*)d_in[11];
    const float* bo    = (const float*)d_in[12];
    const float* tb    = (const float*)d_in[13];

    float *qb, *kb, *vb, *ob, *rp, *pfb, *aofb;
    __half *wldh, *eh;
    unsigned* mpk;
    cudaGetSymbolAddress((void**)&qb,   g_Q);
    cudaGetSymbolAddress((void**)&kb,   g_K);
    cudaGetSymbolAddress((void**)&vb,   g_V);
    cudaGetSymbolAddress((void**)&ob,   g_O);
    cudaGetSymbolAddress((void**)&wldh, g_WLDh);
    cudaGetSymbolAddress((void**)&mpk,  g_MPK);
    cudaGetSymbolAddress((void**)&rp,   g_RP);
    cudaGetSymbolAddress((void**)&eh,   g_Eh);
    cudaGetSymbolAddress((void**)&pfb,  g_Pfb);
    cudaGetSymbolAddress((void**)&aofb, g_AOfb);

    const long long OUT_ATTN = (long long)B_ * S_ * E_;      // 2,097,152
    const long long W_EL     = (long long)BH_ * S_ * S_;     // 67,108,864
    const long long osz      = (long long)out_size;

    float* attn_out;
    float* P;
    if (osz >= OUT_ATTN + W_EL) {            // tuple output: (attn_output, attn_weights)
        attn_out = (float*)d_out;
        P        = (float*)d_out + OUT_ATTN;
    } else if (osz == W_EL) {                // weights-only output
        P        = (float*)d_out;
        attn_out = aofb;
    } else {                                  // attn_output-only output
        attn_out = (float*)d_out;
        P        = pfb;
    }

    dim3 blk(128);
    expld_kernel<<<dim3((S_ * S_) / (256 * 8)), dim3(256)>>>(ld, wldh);
    packmask_kernel<<<dim3((S_ * S_ / 32) / 256), dim3(256)>>>(mask, mpk);
    qkv_kernel<<<dim3(8, 64, 3), blk>>>(query, key, value,
                                        Wq, Wk, Wv, bq, bk, bv,
                                        qb, kb, vb);
    scores_kernel<<<dim3(32, 32, 16), blk>>>(qb, kb, mpk, (const __half2*)wldh, tb, eh, rp);
    av_kernel<<<dim3(1, 32, 16), blk>>>(eh, vb, rp, P, ob);
    oproj_kernel<<<dim3(8, 64), blk>>>(ob, Wo, bo, attn_out);
}

// round 17
// speedup vs baseline: 1.1221x; 1.1221x over previous
#include <cuda_runtime.h>
#include <cuda_fp16.h>
#include <cstdint>
#include <cstddef>

// Problem constants
#define S_   2048
#define E_   512
#define H_   8
#define DH_  64
#define B_   2
#define BH_  16          // B_*H_
#define SCALE_ 0.125f    // DH^-0.5

// ---------------- scratch (__device__ globals: allocation-free) ----------------
__device__ float    g_Q  [BH_ * S_ * DH_];          // 8 MB
__device__ float    g_K  [BH_ * S_ * DH_];          // 8 MB
__device__ float    g_V  [BH_ * S_ * DH_];          // 8 MB
__device__ float    g_O  [BH_ * S_ * DH_];          // 8 MB
__device__ __half   g_WLDh[(size_t)S_ * S_];        // 8 MB: exp(-layer_distances) in fp16
__device__ unsigned g_MPK[(size_t)S_ * S_ / 32];    // 512 KB: mask packed 1 bit/elem
__device__ float    g_RP [(size_t)BH_ * S_ * 32];   // 4 MB: per-row partial sums (32 n-blocks)
__device__ __half   g_Eh [(size_t)BH_ * S_ * S_];   // 134 MB: unnormalized exp-scores (fp16)
__device__ float    g_Pfb[(size_t)BH_ * S_ * S_];   // 268 MB fallback if weights not in d_out
__device__ float    g_AOfb[B_ * S_ * E_];           // fallback attn_output sink

// ---------------- tf32 mma helpers ----------------
__device__ __forceinline__ uint32_t f2tf(float x) {
    uint32_t u;
    asm("cvt.rna.tf32.f32 %0, %1;" : "=r"(u) : "f"(x));
    return u;
}

// hi/lo split for 3xTF32: x ~= hi + lo, both exactly representable in tf32.
__device__ __forceinline__ void split_tf(float x, uint32_t& hi, uint32_t& lo) {
    hi = f2tf(x);
    lo = f2tf(x - __uint_as_float(hi));
}

__device__ __forceinline__ void mma8(float c[4], const uint32_t a[4], const uint32_t b[2]) {
    asm volatile(
        "mma.sync.aligned.m16n8k8.row.col.f32.tf32.tf32.f32 "
        "{%0,%1,%2,%3},{%4,%5,%6,%7},{%8,%9},{%0,%1,%2,%3};"
        : "+f"(c[0]), "+f"(c[1]), "+f"(c[2]), "+f"(c[3])
        : "r"(a[0]), "r"(a[1]), "r"(a[2]), "r"(a[3]), "r"(b[0]), "r"(b[1]));
}

// streaming (evict-first) load/store helpers
__device__ __forceinline__ void stcs4(float* p, float4 v) { __stcs((float4*)p, v); }
__device__ __forceinline__ uint2 ldcs_u2(const void* p) { return __ldcs((const uint2*)p); }
__device__ __forceinline__ void stcs_u4(void* p, uint4 v) { __stcs((uint4*)p, v); }

// 64x64 block tile, 4 warps (2x2), each warp 32x32 = 2(m) x 4(n) m16n8k8 tiles.
// Smem tiles are [64][36] (stride-36 pad -> conflict-free fragment loads:
// bank = (4*grp + tig + kk) % 32, all lanes distinct).
// 3xTF32 variant: ~fp32 accuracy. ah*bh + ah*bl + al*bh.
__device__ __forceinline__ void mma_tile3x(const float As[64][36], const float Bs[64][36],
                                           float acc[2][4][4], int wm, int wn, int grp, int tig) {
#pragma unroll
    for (int kk = 0; kk < 32; kk += 8) {
        uint32_t ah[2][4], al[2][4], bh[4][2], bl[4][2];
#pragma unroll
        for (int mt = 0; mt < 2; mt++) {
            int r = wm * 32 + mt * 16 + grp;
            split_tf(As[r    ][kk + tig    ], ah[mt][0], al[mt][0]);
            split_tf(As[r + 8][kk + tig    ], ah[mt][1], al[mt][1]);
            split_tf(As[r    ][kk + tig + 4], ah[mt][2], al[mt][2]);
            split_tf(As[r + 8][kk + tig + 4], ah[mt][3], al[mt][3]);
        }
#pragma unroll
        for (int nt = 0; nt < 4; nt++) {
            int c = wn * 32 + nt * 8 + grp;
            split_tf(Bs[c][kk + tig    ], bh[nt][0], bl[nt][0]);
            split_tf(Bs[c][kk + tig + 4], bh[nt][1], bl[nt][1]);
        }
#pragma unroll
        for (int mt = 0; mt < 2; mt++)
#pragma unroll
            for (int nt = 0; nt < 4; nt++) {
                mma8(acc[mt][nt], ah[mt], bl[nt]);
                mma8(acc[mt][nt], al[mt], bh[nt]);
                mma8(acc[mt][nt], ah[mt], bh[nt]);
            }
    }
}

// 1xTF32 variant (~tf32 accuracy, 1/3 tensor cycles) for error-tolerant GEMMs.
__device__ __forceinline__ void mma_tile1x(const float As[64][36], const float Bs[64][36],
                                           float acc[2][4][4], int wm, int wn, int grp, int tig) {
#pragma unroll
    for (int kk = 0; kk < 32; kk += 8) {
        uint32_t a[2][4], b[4][2];
#pragma unroll
        for (int mt = 0; mt < 2; mt++) {
            int r = wm * 32 + mt * 16 + grp;
            a[mt][0] = f2tf(As[r    ][kk + tig    ]);
            a[mt][1] = f2tf(As[r + 8][kk + tig    ]);
            a[mt][2] = f2tf(As[r    ][kk + tig + 4]);
            a[mt][3] = f2tf(As[r + 8][kk + tig + 4]);
        }
#pragma unroll
        for (int nt = 0; nt < 4; nt++) {
            int c = wn * 32 + nt * 8 + grp;
            b[nt][0] = f2tf(Bs[c][kk + tig    ]);
            b[nt][1] = f2tf(Bs[c][kk + tig + 4]);
        }
#pragma unroll
        for (int mt = 0; mt < 2; mt++)
#pragma unroll
            for (int nt = 0; nt < 4; nt++)
                mma8(acc[mt][nt], a[mt], b[nt]);
    }
}

// ---------------- kernel 0a: WLDh = half(exp(-layer_distances)), computed once --------------
__global__ __launch_bounds__(256) void expld_kernel(const float* __restrict__ ld,
                                                    __half* __restrict__ w) {
    size_t i = ((size_t)blockIdx.x * 256 + threadIdx.x) * 8;
    float4 a = *(const float4*)&ld[i];
    float4 b = *(const float4*)&ld[i + 4];
    __half2 h0 = __floats2half2_rn(__expf(-a.x), __expf(-a.y));
    __half2 h1 = __floats2half2_rn(__expf(-a.z), __expf(-a.w));
    __half2 h2 = __floats2half2_rn(__expf(-b.x), __expf(-b.y));
    __half2 h3 = __floats2half2_rn(__expf(-b.z), __expf(-b.w));
    uint4 o;
    o.x = *reinterpret_cast<uint32_t*>(&h0);
    o.y = *reinterpret_cast<uint32_t*>(&h1);
    o.z = *reinterpret_cast<uint32_t*>(&h2);
    o.w = *reinterpret_cast<uint32_t*>(&h3);
    *reinterpret_cast<uint4*>(w + i) = o;
}

// ---------------- kernel 0b: pack mask to 1 bit/element, computed once ----------------
__global__ __launch_bounds__(256) void packmask_kernel(const int* __restrict__ mask,
                                                       unsigned* __restrict__ mpk) {
    int w = blockIdx.x * 256 + threadIdx.x;
    const int* base = mask + (size_t)w * 32;
    unsigned bits = 0;
#pragma unroll
    for (int j = 0; j < 8; j++) {
        int4 v = *(const int4*)(base + j * 4);
        bits |= (v.x != 0 ? 1u : 0u) << (j * 4 + 0);
        bits |= (v.y != 0 ? 1u : 0u) << (j * 4 + 1);
        bits |= (v.z != 0 ? 1u : 0u) << (j * 4 + 2);
        bits |= (v.w != 0 ? 1u : 0u) << (j * 4 + 3);
    }
    mpk[w] = bits;
}

// ---------------- kernel 1: fused QKV projection (double-buffered) ----------------
// blockIdx.z in {0,1,2} selects (X, W, bias, out). grid (8, 64, 3), 128 threads.
// Q/K use 3xTF32 (feed exp -> abs-error sensitive); V uses 1x (feeds attn_output, tolerant).
__global__ __launch_bounds__(128) void qkv_kernel(
    const float* __restrict__ Xq, const float* __restrict__ Xk, const float* __restrict__ Xv,
    const float* __restrict__ Wq, const float* __restrict__ Wk, const float* __restrict__ Wv,
    const float* __restrict__ bq, const float* __restrict__ bk, const float* __restrict__ bv,
    float* __restrict__ oq, float* __restrict__ ok, float* __restrict__ ov) {
    const int z = blockIdx.z;
    const float* X    = (z == 0) ? Xq : (z == 1) ? Xk : Xv;
    const float* W    = (z == 0) ? Wq : (z == 1) ? Wk : Wv;
    const float* bias = (z == 0) ? bq : (z == 1) ? bk : bv;
    float*       out  = (z == 0) ? oq : (z == 1) ? ok : ov;

    __shared__ float As[64][36];
    __shared__ float Bs[64][36];
    const int t = threadIdx.x;
    const int lane = t & 31, warp = t >> 5;
    const int wm = warp >> 1, wn = warp & 1;
    const int grp = lane >> 2, tig = lane & 3;
    const int m0 = blockIdx.y * 64, n0 = blockIdx.x * 64;

    int rowT[4], c4T[4];
#pragma unroll
    for (int i = 0; i < 4; i++) {
        int idx = t + i * 128;
        rowT[i] = idx >> 3; c4T[i] = idx & 7;
    }

    float4 xR[4], wR[4];
#pragma unroll
    for (int i = 0; i < 4; i++) {
        xR[i] = *(const float4*)&X[(size_t)(m0 + rowT[i]) * 512 + c4T[i] * 4];
        wR[i] = *(const float4*)&W[(size_t)(n0 + rowT[i]) * 512 + c4T[i] * 4];
    }

    float acc[2][4][4] = {};
    for (int k0 = 0; k0 < 512; k0 += 32) {
#pragma unroll
        for (int i = 0; i < 4; i++) {
            *(float4*)&As[rowT[i]][c4T[i] * 4] = xR[i];
            *(float4*)&Bs[rowT[i]][c4T[i] * 4] = wR[i];
        }
        if (k0 + 32 < 512) {
#pragma unroll
            for (int i = 0; i < 4; i++) {
                xR[i] = *(const float4*)&X[(size_t)(m0 + rowT[i]) * 512 + (k0 + 32) + c4T[i] * 4];
                wR[i] = *(const float4*)&W[(size_t)(n0 + rowT[i]) * 512 + (k0 + 32) + c4T[i] * 4];
            }
        }
        __syncthreads();
        if (z < 2) mma_tile3x(As, Bs, acc, wm, wn, grp, tig);
        else       mma_tile1x(As, Bs, acc, wm, wn, grp, tig);
        __syncthreads();
    }
#pragma unroll
    for (int mt = 0; mt < 2; mt++) {
#pragma unroll
        for (int nt = 0; nt < 4; nt++) {
            int n = n0 + wn * 32 + nt * 8 + tig * 2;
            float bv0 = bias[n], bv1 = bias[n + 1];
            int h = n >> 6, d = n & 63;
#pragma unroll
            for (int rr = 0; rr < 2; rr++) {
                int m = m0 + wm * 32 + mt * 16 + grp + rr * 8;
                int bb = m >> 11, s = m & 2047;
                float2 o;
                o.x = acc[mt][nt][rr * 2 + 0] + bv0;
                o.y = acc[mt][nt][rr * 2 + 1] + bv1;
                *(float2*)&out[(((size_t)(bb * H_ + h)) * S_ + s) * DH_ + d] = o;
            }
        }
    }
}

// ---------------- kernel 2: Eh = half(exp(QK^T*SCALE + tb[h]*WLD)), mask->0 (3xTF32) --------
// STAGED EPILOGUE (targets the measured L1=66.9% bottleneck): wld tile is loaded coalesced
// into smem; exp results are written to a smem half-tile (conflict-free 72-stride) then
// stored coalesced (128B rows, streaming). RP sums from fp32 values BEFORE quantization.
// Per (b,h): grid (32, 32, 16), 128 threads.
__global__ __launch_bounds__(128) void scores_kernel(
    const float* __restrict__ Q, const float* __restrict__ Kt,
    const unsigned* __restrict__ mpk, const __half* __restrict__ wldh,
    const float* __restrict__ tb, __half* __restrict__ Eh, float* __restrict__ RP) {
    __shared__ float As[64][36];
    __shared__ float Bs[64][36];
    __shared__ float sumbuf[64][2];
    const int t = threadIdx.x;
    const int lane = t & 31, warp = t >> 5;
    const int wm = warp >> 1, wn = warp & 1;
    const int grp = lane >> 2, tig = lane & 3;
    const int bh = blockIdx.z;
    const float* Qb  = Q  + (size_t)bh * S_ * DH_;
    const float* Kb  = Kt + (size_t)bh * S_ * DH_;
    __half*      Eb  = Eh + (size_t)bh * S_ * S_;
    const float  tbh = tb[bh & (H_ - 1)];
    const int m0 = blockIdx.y * 64, n0 = blockIdx.x * 64;

    float acc[2][4][4] = {};
    for (int k0 = 0; k0 < 64; k0 += 32) {
#pragma unroll
        for (int i = 0; i < 4; i++) {
            int idx = t + i * 128, row = idx >> 3, c4 = idx & 7;
            *(float4*)&As[row][c4 * 4] = *(const float4*)&Qb[(size_t)(m0 + row) * 64 + k0 + c4 * 4];
            *(float4*)&Bs[row][c4 * 4] = *(const float4*)&Kb[(size_t)(n0 + row) * 64 + k0 + c4 * 4];
        }
        __syncthreads();
        mma_tile3x(As, Bs, acc, wm, wn, grp, tig);
        __syncthreads();
    }

    // ---- staged epilogue: mma tiles are dead; reuse as half[64][72] (9216 B each, exact) ----
    __half (*Wt)[72] = reinterpret_cast<__half (*)[72]>(Bs);  // wld tile
    __half (*Et)[72] = reinterpret_cast<__half (*)[72]>(As);  // exp-result tile

    // 1. coalesced load of the 64x64 wld half-tile (128 B per row)
#pragma unroll
    for (int i = 0; i < 4; i++) {
        int idx = t + i * 128, row = idx >> 3, ch = idx & 7;
        const char* src = (const char*)wldh + ((size_t)(m0 + row) * S_ + n0) * 2 + ch * 16;
        *(uint4*)&Wt[row][ch * 8] = *(const uint4*)src;
    }
    __syncthreads();

    // 2. fragment epilogue: read wld from smem, write exp results to smem (both conflict-free:
    //    half2 word index = 36*row + n/2 -> bank = (4*grp + tig) mod 32, all lanes distinct)
#pragma unroll
    for (int mt = 0; mt < 2; mt++) {
#pragma unroll
        for (int rr = 0; rr < 2; rr++) {
            const int lrow = wm * 32 + mt * 16 + grp + rr * 8;
            const int m = m0 + lrow;
            const unsigned mw = mpk[m * (S_ / 32) + (n0 >> 5) + wn];
            float psum = 0.f;
#pragma unroll
            for (int nt = 0; nt < 4; nt++) {
                int ln = wn * 32 + nt * 8 + tig * 2;
                float2 wv = __half22float2(*(__half2*)&Wt[lrow][ln]);
                int bit = nt * 8 + tig * 2;
                float s0 = acc[mt][nt][rr * 2 + 0] * SCALE_ + tbh * wv.x;
                float s1 = acc[mt][nt][rr * 2 + 1] * SCALE_ + tbh * wv.y;
                float ex = ((mw >> bit) & 1u)       ? __expf(s0) : 0.f;
                float ey = ((mw >> (bit + 1)) & 1u) ? __expf(s1) : 0.f;
                *(__half2*)&Et[lrow][ln] = __floats2half2_rn(ex, ey);
                psum += ex + ey;   // fp32 sum, pre-quantization
            }
            psum += __shfl_xor_sync(0xffffffffu, psum, 1);
            psum += __shfl_xor_sync(0xffffffffu, psum, 2);
            if (tig == 0) sumbuf[lrow][wn] = psum;
        }
    }
    __syncthreads();
    if (t < 64) {
        RP[((size_t)bh * S_ + (m0 + t)) * 32 + blockIdx.x] = sumbuf[t][0] + sumbuf[t][1];
    }

    // 3. coalesced streaming store of the E tile (128 B per row)
#pragma unroll
    for (int i = 0; i < 4; i++) {
        int idx = t + i * 128, row = idx >> 3, ch = idx & 7;
        uint4 v = *(uint4*)&Et[row][ch * 8];
        stcs_u4((char*)Eb + ((size_t)(m0 + row) * S_ + n0) * 2 + ch * 16, v);
    }
}

// ---------------- kernel 3: read half E, write normalized fp32 P, O = Pn @ V ----------------
// grid (1, 32, 16). E read and P write both streaming; V stays cached.
// Register double-buffer: E/V for k-step k0+32 are prefetched right after the
// smem-store phase of k0, so DRAM latency overlaps the mma + barriers.
__global__ __launch_bounds__(128) void av_kernel(
    const __half* __restrict__ Eh, const float* __restrict__ V,
    const float* __restrict__ RP, float* __restrict__ Pout, float* __restrict__ O) {
    __shared__ float As[64][36];
    __shared__ float Bk[32][68];
    __shared__ float invs[64];
    const int t = threadIdx.x;
    const int lane = t & 31, warp = t >> 5;
    const int wm = warp >> 1, wn = warp & 1;
    const int grp = lane >> 2, tig = lane & 3;
    const int bh = blockIdx.z;
    const __half* Eb = Eh   + (size_t)bh * S_ * S_;
    float*        Pb = Pout + (size_t)bh * S_ * S_;
    const float*  Vb = V    + (size_t)bh * S_ * DH_;
    float*        Ob = O    + (size_t)bh * S_ * DH_;
    const int m0 = blockIdx.y * 64;

    if (t < 64) {
        const float* rp = RP + ((size_t)bh * S_ + (m0 + t)) * 32;
        float s = 0.f;
#pragma unroll
        for (int j = 0; j < 32; j++) s += rp[j];
        invs[t] = 1.0f / s;
    }
    __syncthreads();

    int rowE[4], c4E[4], kkV[4], c4V[4];
#pragma unroll
    for (int i = 0; i < 4; i++) {
        int idx = t + i * 128;
        rowE[i] = idx >> 3;  c4E[i] = idx & 7;
        kkV[i]  = idx >> 4;  c4V[i] = idx & 15;
    }

    uint2  eR[4];
    float4 vR[4];
#pragma unroll
    for (int i = 0; i < 4; i++) {
        eR[i] = ldcs_u2(&Eb[(size_t)(m0 + rowE[i]) * S_ + c4E[i] * 4]);
        vR[i] = *(const float4*)&Vb[(size_t)kkV[i] * 64 + c4V[i] * 4];
    }

    float acc[2][4][4] = {};
    for (int k0 = 0; k0 < S_; k0 += 32) {
#pragma unroll
        for (int i = 0; i < 4; i++) {
            float2 e01 = __half22float2(*reinterpret_cast<__half2*>(&eR[i].x));
            float2 e23 = __half22float2(*reinterpret_cast<__half2*>(&eR[i].y));
            float iv = invs[rowE[i]];
            float4 v;
            v.x = e01.x * iv; v.y = e01.y * iv;
            v.z = e23.x * iv; v.w = e23.y * iv;
            *(float4*)&As[rowE[i]][c4E[i] * 4] = v;
            stcs4(&Pb[(size_t)(m0 + rowE[i]) * S_ + k0 + c4E[i] * 4], v);
            *(float4*)&Bk[kkV[i]][c4V[i] * 4] = vR[i];
        }
        if (k0 + 32 < S_) {
#pragma unroll
            for (int i = 0; i < 4; i++) {
                eR[i] = ldcs_u2(&Eb[(size_t)(m0 + rowE[i]) * S_ + (k0 + 32) + c4E[i] * 4]);
                vR[i] = *(const float4*)&Vb[(size_t)(k0 + 32 + kkV[i]) * 64 + c4V[i] * 4];
            }
        }
        __syncthreads();
#pragma unroll
        for (int kk = 0; kk < 32; kk += 8) {
            uint32_t a[2][4], b[4][2];
#pragma unroll
            for (int mt = 0; mt < 2; mt++) {
                int r = wm * 32 + mt * 16 + grp;
                a[mt][0] = f2tf(As[r    ][kk + tig    ]);
                a[mt][1] = f2tf(As[r + 8][kk + tig    ]);
                a[mt][2] = f2tf(As[r    ][kk + tig + 4]);
                a[mt][3] = f2tf(As[r + 8][kk + tig + 4]);
            }
#pragma unroll
            for (int nt = 0; nt < 4; nt++) {
                int c = wn * 32 + nt * 8 + grp;
                b[nt][0] = f2tf(Bk[kk + tig    ][c]);
                b[nt][1] = f2tf(Bk[kk + tig + 4][c]);
            }
#pragma unroll
            for (int mt = 0; mt < 2; mt++)
#pragma unroll
                for (int nt = 0; nt < 4; nt++)
                    mma8(acc[mt][nt], a[mt], b[nt]);
        }
        __syncthreads();
    }
#pragma unroll
    for (int mt = 0; mt < 2; mt++) {
#pragma unroll
        for (int nt = 0; nt < 4; nt++) {
            int n = wn * 32 + nt * 8 + tig * 2;
#pragma unroll
            for (int rr = 0; rr < 2; rr++) {
                int m = m0 + wm * 32 + mt * 16 + grp + rr * 8;
                float2 o;
                o.x = acc[mt][nt][rr * 2 + 0];
                o.y = acc[mt][nt][rr * 2 + 1];
                *(float2*)&Ob[(size_t)m * 64 + n] = o;
            }
        }
    }
}

// ---------------- kernel 4: output projection (head-gather A, 1xTF32, double-buffered) ------
__global__ __launch_bounds__(128) void oproj_kernel(
    const float* __restrict__ O, const float* __restrict__ W,
    const float* __restrict__ bias, float* __restrict__ out) {
    __shared__ float As[64][36];
    __shared__ float Bs[64][36];
    const int t = threadIdx.x;
    const int lane = t & 31, warp = t >> 5;
    const int wm = warp >> 1, wn = warp & 1;
    const int grp = lane >> 2, tig = lane & 3;
    const int m0 = blockIdx.y * 64, n0 = blockIdx.x * 64;

    int rowT[4], c4T[4];
#pragma unroll
    for (int i = 0; i < 4; i++) {
        int idx = t + i * 128;
        rowT[i] = idx >> 3; c4T[i] = idx & 7;
    }

    auto loadA = [&](int i, int k0) -> float4 {
        int m = m0 + rowT[i];
        int bb = m >> 11, s = m & 2047;
        int kk = k0 + c4T[i] * 4;
        int h = kk >> 6, d = kk & 63;
        return *(const float4*)&O[(((size_t)(bb * H_ + h)) * S_ + s) * DH_ + d];
    };

    float4 aR[4], wR[4];
#pragma unroll
    for (int i = 0; i < 4; i++) {
        aR[i] = loadA(i, 0);
        wR[i] = *(const float4*)&W[(size_t)(n0 + rowT[i]) * 512 + c4T[i] * 4];
    }

    float acc[2][4][4] = {};
    for (int k0 = 0; k0 < 512; k0 += 32) {
#pragma unroll
        for (int i = 0; i < 4; i++) {
            *(float4*)&As[rowT[i]][c4T[i] * 4] = aR[i];
            *(float4*)&Bs[rowT[i]][c4T[i] * 4] = wR[i];
        }
        if (k0 + 32 < 512) {
#pragma unroll
            for (int i = 0; i < 4; i++) {
                aR[i] = loadA(i, k0 + 32);
                wR[i] = *(const float4*)&W[(size_t)(n0 + rowT[i]) * 512 + (k0 + 32) + c4T[i] * 4];
            }
        }
        __syncthreads();
        mma_tile1x(As, Bs, acc, wm, wn, grp, tig);
        __syncthreads();
    }
#pragma unroll
    for (int mt = 0; mt < 2; mt++) {
#pragma unroll
        for (int nt = 0; nt < 4; nt++) {
            int n = n0 + wn * 32 + nt * 8 + tig * 2;
            float bv0 = bias[n], bv1 = bias[n + 1];
#pragma unroll
            for (int rr = 0; rr < 2; rr++) {
                int m = m0 + wm * 32 + mt * 16 + grp + rr * 8;
                float2 o;
                o.x = acc[mt][nt][rr * 2 + 0] + bv0;
                o.y = acc[mt][nt][rr * 2 + 1] + bv1;
                *(float2*)&out[(size_t)m * 512 + n] = o;
            }
        }
    }
}

// ---------------- host launcher ----------------
extern "C" void kernel_launch(void* const* d_in, const int* in_sizes, int n_in,
                              void* d_out, int out_size) {
    const float* query = (const float*)d_in[0];
    const float* key   = (const float*)d_in[1];
    const float* value = (const float*)d_in[2];
    const int*   mask  = (const int*)d_in[3];
    const float* ld    = (const float*)d_in[4];
    const float* Wq    = (const float*)d_in[5];
    const float* bq    = (const float*)d_in[6];
    const float* Wk    = (const float*)d_in[7];
    const float* bk    = (const float*)d_in[8];
    const float* Wv    = (const float*)d_in[9];
    const float* bv    = (const float*)d_in[10];
    const float* Wo    = (const float*)d_in[11];
    const float* bo    = (const float*)d_in[12];
    const float* tb    = (const float*)d_in[13];

    float *qb, *kb, *vb, *ob, *rp, *pfb, *aofb;
    __half *wldh, *eh;
    unsigned* mpk;
    cudaGetSymbolAddress((void**)&qb,   g_Q);
    cudaGetSymbolAddress((void**)&kb,   g_K);
    cudaGetSymbolAddress((void**)&vb,   g_V);
    cudaGetSymbolAddress((void**)&ob,   g_O);
    cudaGetSymbolAddress((void**)&wldh, g_WLDh);
    cudaGetSymbolAddress((void**)&mpk,  g_MPK);
    cudaGetSymbolAddress((void**)&rp,   g_RP);
    cudaGetSymbolAddress((void**)&eh,   g_Eh);
    cudaGetSymbolAddress((void**)&pfb,  g_Pfb);
    cudaGetSymbolAddress((void**)&aofb, g_AOfb);

    const long long OUT_ATTN = (long long)B_ * S_ * E_;      // 2,097,152
    const long long W_EL     = (long long)BH_ * S_ * S_;     // 67,108,864
    const long long osz      = (long long)out_size;

    float* attn_out;
    float* P;
    if (osz >= OUT_ATTN + W_EL) {            // tuple output: (attn_output, attn_weights)
        attn_out = (float*)d_out;
        P        = (float*)d_out + OUT_ATTN;
    } else if (osz == W_EL) {                // weights-only output
        P        = (float*)d_out;
        attn_out = aofb;
    } else {                                  // attn_output-only output
        attn_out = (float*)d_out;
        P        = pfb;
    }

    dim3 blk(128);
    expld_kernel<<<dim3((S_ * S_) / (256 * 8)), dim3(256)>>>(ld, wldh);
    packmask_kernel<<<dim3((S_ * S_ / 32) / 256), dim3(256)>>>(mask, mpk);
    qkv_kernel<<<dim3(8, 64, 3), blk>>>(query, key, value,
                                        Wq, Wk, Wv, bq, bk, bv,
                                        qb, kb, vb);
    scores_kernel<<<dim3(32, 32, 16), blk>>>(qb, kb, mpk, wldh, tb, eh, rp);
    av_kernel<<<dim3(1, 32, 16), blk>>>(eh, vb, rp, P, ob);
    oproj_kernel<<<dim3(8, 64), blk>>>(ob, Wo, bo, attn_out);
}